// round 15
// baseline (speedup 1.0000x reference)
#include <cuda_runtime.h>
#include <cstdint>
#include <cstddef>

// Problem shapes (fixed by the dataset)
#define NB 64          // batch
#define NL 512         // sequence length
#define ND 50          // embedding dim
#define NDP 56         // padded dim (halves of 28 floats, 16B-aligned)
#define NDH 28         // half-dim per lane group
#define NM 128         // number of measurement kernels
#define LCHUNK 64      // tokens per k_main CTA
#define NCHUNK (NL / LCHUNK)   // 8
#define TROW (3 * NDP) // floats per token in smem: vr[56] | vi[56] | (vr+vi)[56]

// ---------------- device-global scratch (no runtime allocation) ----------------
__device__ float g_sw[NB * NL];                   // sqrt(exp(mix)) per token
__device__ float g_einv[NB];                      // 1 / sum_l exp(mix) per batch
__device__ __align__(16) float g_ka [NM * NDP];   // kr_n          (padded, zeros)
__device__ __align__(16) float g_kb [NM * NDP];   // -ki_n
__device__ __align__(16) float g_kab[NM * NDP];   // kr_n - ki_n

// packed f32x2 helpers (Blackwell sm_103a)
__device__ __forceinline__ float2 up2(unsigned long long v) {
    float2 r;
    asm("mov.b64 {%0, %1}, %2;" : "=f"(r.x), "=f"(r.y) : "l"(v));
    return r;
}
#define FMA2(d, a, b) asm("fma.rn.f32x2 %0, %1, %2, %0;" : "+l"(d) : "l"(a), "l"(b))

// ---------------- K0: per-batch exp-sum + kernel normalization ----------------
// blocks 0..63: e = exp(mix[x]) for batch b, block-sum -> g_einv; sqrt(e) -> g_sw.
// block 64: normalize measurement kernels, build Karatsuba row triplets.
__global__ void k_prep(const int* __restrict__ x, const float* __restrict__ mix,
                       const float* __restrict__ kr, const float* __restrict__ ki) {
    int b = blockIdx.x;
    int t = threadIdx.x;

    if (b == NB) {
        if (t < NM) {
            float s = 0.f;
#pragma unroll
            for (int d = 0; d < ND; d++) {
                float a = kr[t * ND + d];
                float c = ki[t * ND + d];
                s = fmaf(a, a, s);
                s = fmaf(c, c, s);
            }
            float rn = rsqrtf(s);
#pragma unroll
            for (int d = 0; d < NDP; d++) {
                float a = (d < ND) ? kr[t * ND + d] * rn : 0.f;
                float c = (d < ND) ? ki[t * ND + d] * rn : 0.f;
                g_ka [t * NDP + d] = a;
                g_kb [t * NDP + d] = -c;
                g_kab[t * NDP + d] = a - c;
            }
        }
        return;
    }

    // softmax numerator without max-shift: mix ~ N(0,1), exp is safe in fp32
    float e = __expf(mix[x[b * NL + t]]);

    __shared__ float red[16];
    float s = e;
#pragma unroll
    for (int o = 16; o > 0; o >>= 1) s += __shfl_xor_sync(0xffffffffu, s, o);
    if ((t & 31) == 0) red[t >> 5] = s;
    __syncthreads();
    if (t < 16) {
        float ss = red[t];
#pragma unroll
        for (int o = 8; o > 0; o >>= 1) ss += __shfl_xor_sync(0x0000ffffu, ss, o);
        if (t == 0) g_einv[b] = 1.f / ss;
    }
    g_sw[b * NL + t] = sqrtf(e);
}

// ---------------- K1: fused gather + contraction ----------------
// grid = NB*NCHUNK CTAs, 256 threads. Warp w owns m = w*16 + (lane&15);
// lane half h = lane>>4 owns dims [h*28, h*28+28). Karatsuba row triplet
// (a, b=-ki, a+b) lives in 84 registers (3 x 14 f32x2).
// Gather: each CTA converts its 64 tokens (amp*exp(i*pha), scaled by sqrt(e))
// straight into smem — vr | vi | vr+vi per token.
// Per token: M1=sum a*vr, M2=sum b*vi, M3=sum(a+b)(vr+vi) over own half;
// combine halves via shfl.xor 16; ar=M1-M2, ai=M3-M1-M2; acc += ar^2+ai^2.
// Final: atomicAdd(out[b,m], acc * (1/sum e)).
__global__ void __launch_bounds__(256, 2) k_main(const int* __restrict__ x,
                                                 const float* __restrict__ amp,
                                                 const float* __restrict__ pha,
                                                 float* __restrict__ out) {
    __shared__ __align__(16) float sv[LCHUNK * TROW];   // 64*168*4 = 43008 B

    int b = blockIdx.x >> 3;     // / NCHUNK
    int c = blockIdx.x & 7;      // % NCHUNK
    int t = threadIdx.x;
    int lane = t & 31;
    int w = t >> 5;
    int h  = lane >> 4;                       // dim half
    int mi = (w << 4) | (lane & 15);          // m index 0..127

    // ---- load this thread's Karatsuba half-row triplet into registers ----
    unsigned long long ka2[NDH / 2], kb2[NDH / 2], kab2[NDH / 2];
    {
        const ulonglong2* pa = (const ulonglong2*)(g_ka  + mi * NDP + h * NDH);
        const ulonglong2* pb = (const ulonglong2*)(g_kb  + mi * NDP + h * NDH);
        const ulonglong2* pc = (const ulonglong2*)(g_kab + mi * NDP + h * NDH);
#pragma unroll
        for (int i = 0; i < NDH / 4; i++) {
            ulonglong2 u = pa[i]; ka2 [2 * i] = u.x; ka2 [2 * i + 1] = u.y;
            ulonglong2 v = pb[i]; kb2 [2 * i] = v.x; kb2 [2 * i + 1] = v.y;
            ulonglong2 q = pc[i]; kab2[2 * i] = q.x; kab2[2 * i + 1] = q.y;
        }
    }

    // ---- fused gather: one warp per token, 8 tokens per warp ----
    int tok0 = b * NL + c * LCHUNK;
#pragma unroll
    for (int i = 0; i < LCHUNK / 8; i++) {
        int tl  = i * 8 + w;
        int tok = tok0 + tl;
        int idx = x[tok];
        float sw = g_sw[tok];

        const float* a_ = amp + (size_t)idx * ND;
        const float* p_ = pha + (size_t)idx * ND;
        float* dst = sv + tl * TROW;

        float a0 = a_[lane];
        float p0 = p_[lane];
        float s, cs;
        __sincosf(p0, &s, &cs);
        float as = a0 * sw;
        float vr = as * cs, vi = as * s;
        dst[lane]           = vr;
        dst[NDP + lane]     = vi;
        dst[2 * NDP + lane] = vr + vi;

        if (lane < NDP - 32) {               // lanes 0..23 cover d=32..55
            float vr1 = 0.f, vi1 = 0.f;
            if (lane < ND - 32) {            // lanes 0..17: real data d=32..49
                float a1 = a_[lane + 32];
                float p1 = p_[lane + 32];
                __sincosf(p1, &s, &cs);
                float as1 = a1 * sw;
                vr1 = as1 * cs;
                vi1 = as1 * s;
            }
            dst[32 + lane]           = vr1;  // d=50..55 -> zeros
            dst[NDP + 32 + lane]     = vi1;
            dst[2 * NDP + 32 + lane] = vr1 + vi1;
        }
    }
    __syncthreads();

    // ---- main contraction ----
    float acc = 0.f;
#pragma unroll 2
    for (int l = 0; l < LCHUNK; l++) {
        const float* base = sv + l * TROW + h * NDH;
        const ulonglong2* vr = (const ulonglong2*)(base);
        const ulonglong2* vi = (const ulonglong2*)(base + NDP);
        const ulonglong2* vs = (const ulonglong2*)(base + 2 * NDP);
        unsigned long long M1 = 0ull, M2 = 0ull, M3 = 0ull;
#pragma unroll
        for (int k = 0; k < NDH / 4; k++) {
            ulonglong2 r  = vr[k];
            ulonglong2 ii = vi[k];
            ulonglong2 ss = vs[k];
            FMA2(M1, ka2 [2 * k],     r.x);
            FMA2(M2, kb2 [2 * k],     ii.x);
            FMA2(M3, kab2[2 * k],     ss.x);
            FMA2(M1, ka2 [2 * k + 1], r.y);
            FMA2(M2, kb2 [2 * k + 1], ii.y);
            FMA2(M3, kab2[2 * k + 1], ss.y);
        }
        float2 f1 = up2(M1), f2 = up2(M2), f3 = up2(M3);
        float m1 = f1.x + f1.y;
        float m2 = f2.x + f2.y;
        float m3 = f3.x + f3.y;
        m1 += __shfl_xor_sync(0xffffffffu, m1, 16);
        m2 += __shfl_xor_sync(0xffffffffu, m2, 16);
        m3 += __shfl_xor_sync(0xffffffffu, m3, 16);
        float ar = m1 - m2;             // sum kr*vr + ki*vi
        float ai = m3 - m1 - m2;        // sum kr*vi - ki*vr
        acc = fmaf(ar, ar, acc);
        acc = fmaf(ai, ai, acc);
    }

    if (h == 0) atomicAdd(&out[b * NM + mi], acc * g_einv[b]);
}

// ---------------- entry point ----------------
extern "C" void kernel_launch(void* const* d_in, const int* in_sizes, int n_in,
                              void* d_out, int out_size) {
    const int*   x   = (const int*)  d_in[0];   // [B, L] int32
    const float* amp = (const float*)d_in[1];   // [VOCAB, D]
    const float* pha = (const float*)d_in[2];   // [VOCAB, D]
    const float* mix = (const float*)d_in[3];   // [VOCAB, 1]
    const float* kr  = (const float*)d_in[4];   // [M, D]
    const float* ki  = (const float*)d_in[5];   // [M, D]
    float* out = (float*)d_out;                 // [B, M]

    cudaMemsetAsync(out, 0, (size_t)NB * NM * sizeof(float));
    k_prep<<<NB + 1, NL>>>(x, mix, kr, ki);     // +1 block builds kernel rows
    k_main<<<NB * NCHUNK, 256>>>(x, amp, pha, out);
}

// round 16
// speedup vs baseline: 1.0207x; 1.0207x over previous
#include <cuda_runtime.h>
#include <cstdint>
#include <cstddef>

// Problem shapes (fixed by the dataset)
#define NB 64          // batch
#define NL 512         // sequence length
#define ND 50          // embedding dim
#define NDP 56         // padded dim (4 quarters of 14 floats)
#define NDQ 14         // quarter-dim per lane group
#define NM 128         // number of measurement kernels
#define LCHUNK 64      // tokens per k_main CTA
#define NCHUNK (NL / LCHUNK)   // 8
#define TROW (2 * NDP) // floats per token row in g_v: vr[56] | vi[56]

// ---------------- device-global scratch (no runtime allocation) ----------------
__device__ float g_sw[NB * NL];                   // sqrt(exp(mix)) per token
__device__ float g_einv[NB];                      // 1 / sum_l exp(mix) per batch
__device__ __align__(16) float g_ka[NM * NDP];    // kr_n (normalized, padded w/ zeros)
__device__ __align__(16) float g_kb[NM * NDP];    // ki_n
__device__ __align__(16) float4 g_v4[(size_t)NB * NL * TROW / 4];  // scaled vr|vi (~14.7MB)

// packed f32x2 helpers (Blackwell sm_103a)
__device__ __forceinline__ float2 up2(unsigned long long v) {
    float2 r;
    asm("mov.b64 {%0, %1}, %2;" : "=f"(r.x), "=f"(r.y) : "l"(v));
    return r;
}
#define FMA2(d, a, b) asm("fma.rn.f32x2 %0, %1, %2, %0;" : "+l"(d) : "l"(a), "l"(b))

// ---------------- K0: per-batch exp-sum + kernel normalization ----------------
// blocks 0..63: e = exp(mix[x]) for batch b; block-sum -> g_einv; sqrt(e) -> g_sw.
// block 64: normalize measurement kernels, pad D 50 -> 56.
__global__ void k_prep(const int* __restrict__ x, const float* __restrict__ mix,
                       const float* __restrict__ kr, const float* __restrict__ ki) {
    int b = blockIdx.x;
    int t = threadIdx.x;

    if (b == NB) {
        if (t < NM) {
            float s = 0.f;
#pragma unroll
            for (int d = 0; d < ND; d++) {
                float a = kr[t * ND + d];
                float c = ki[t * ND + d];
                s = fmaf(a, a, s);
                s = fmaf(c, c, s);
            }
            float rn = rsqrtf(s);
#pragma unroll
            for (int d = 0; d < NDP; d++) {
                g_ka[t * NDP + d] = (d < ND) ? kr[t * ND + d] * rn : 0.f;
                g_kb[t * NDP + d] = (d < ND) ? ki[t * ND + d] * rn : 0.f;
            }
        }
        return;
    }

    // softmax numerator without max-shift: mix ~ N(0,1), exp is safe in fp32
    float e = __expf(mix[x[b * NL + t]]);

    __shared__ float red[16];
    float s = e;
#pragma unroll
    for (int o = 16; o > 0; o >>= 1) s += __shfl_xor_sync(0xffffffffu, s, o);
    if ((t & 31) == 0) red[t >> 5] = s;
    __syncthreads();
    if (t < 16) {
        float ss = red[t];
#pragma unroll
        for (int o = 8; o > 0; o >>= 1) ss += __shfl_xor_sync(0x0000ffffu, ss, o);
        if (t == 0) g_einv[b] = 1.f / ss;
    }
    g_sw[b * NL + t] = sqrtf(e);
}

// ---------------- K1: gather + convert: v = sqrt(e) * amp * exp(i*pha) ----------------
// one warp per token; lane covers d=lane and d=lane+32; pad d=50..55 with zeros
__global__ void k_gather(const int* __restrict__ x,
                         const float* __restrict__ amp,
                         const float* __restrict__ pha) {
    int tok  = blockIdx.x * 8 + (threadIdx.x >> 5);   // 0..32767
    int lane = threadIdx.x & 31;

    int idx  = x[tok];
    float sw = g_sw[tok];

    const float* a_ = amp + (size_t)idx * ND;
    const float* p_ = pha + (size_t)idx * ND;
    float* dst = (float*)g_v4 + (size_t)tok * TROW;

    float a0 = a_[lane];
    float p0 = p_[lane];
    float a1 = 0.f, p1 = 0.f;
    if (lane < ND - 32) { a1 = a_[lane + 32]; p1 = p_[lane + 32]; }

    float s, c;
    __sincosf(p0, &s, &c);
    float amp0 = a0 * sw;
    dst[lane]       = amp0 * c;
    dst[NDP + lane] = amp0 * s;

    if (lane < NDP - 32) {                 // lanes 0..23 cover d=32..55
        float vr1 = 0.f, vi1 = 0.f;
        if (lane < ND - 32) {              // lanes 0..17: real data d=32..49
            __sincosf(p1, &s, &c);
            float amp1 = a1 * sw;
            vr1 = amp1 * c;
            vi1 = amp1 * s;
        }
        dst[32 + lane]       = vr1;        // d=50..55 -> zeros
        dst[NDP + 32 + lane] = vi1;
    }
}

// ---------------- K2: main contraction (quarter-row split, 512 threads) ----------------
// Warp w (0..15) owns m = w*8 + (lane&7); lane group q = lane>>3 owns dims
// [q*14, q*14+14). Row quarter = 28 regs (14 x f32x2). Low register footprint
// -> 2 CTAs/SM (32 warps) for latency hiding.
// Per token: P=sum kr*vr, Q=sum ki*vi, R=sum kr*vi, S=sum ki*vr over own quarter;
// ar=P+Q, ai=R-S; reduce over quarters via shfl.xor 8,16; acc += ar^2 + ai^2.
// Final: atomicAdd(out[b,m], acc * (1/sum e)).  (sqrt(e) folded into v)
__global__ void __launch_bounds__(512, 2) k_main(float* __restrict__ out) {
    __shared__ __align__(16) float sv[LCHUNK * TROW];   // 64*112*4 = 28672 B

    int b = blockIdx.x >> 3;     // / NCHUNK
    int c = blockIdx.x & 7;      // % NCHUNK
    int t = threadIdx.x;
    int lane = t & 31;
    int w = t >> 5;                       // 0..15
    int q = lane >> 3;                    // dim quarter 0..3
    int mi = (w << 3) | (lane & 7);       // m index 0..127

    // load this thread's quarter-row into registers as f32x2 pairs (LDG.64)
    unsigned long long ka[NDQ / 2], kb[NDQ / 2];
    {
        const unsigned long long* pa = (const unsigned long long*)(g_ka + mi * NDP + q * NDQ);
        const unsigned long long* pb = (const unsigned long long*)(g_kb + mi * NDP + q * NDQ);
#pragma unroll
        for (int i = 0; i < NDQ / 2; i++) { ka[i] = pa[i]; kb[i] = pb[i]; }
    }

    // cooperatively stage the token tile into shared memory (coalesced float4)
    {
        const float4* src = g_v4 + (size_t)(b * NL + c * LCHUNK) * TROW / 4;
#pragma unroll
        for (int i = t; i < LCHUNK * TROW / 4; i += 512) ((float4*)sv)[i] = src[i];
    }
    __syncthreads();

    float acc = 0.f;

#pragma unroll 1
    for (int l = 0; l < LCHUNK; l++) {
        const unsigned long long* vr =
            (const unsigned long long*)(sv + l * TROW + q * NDQ);
        const unsigned long long* vi =
            (const unsigned long long*)(sv + l * TROW + NDP + q * NDQ);
        unsigned long long P = 0ull, Q = 0ull, R = 0ull, S = 0ull;
#pragma unroll
        for (int k = 0; k < NDQ / 2; k++) {
            unsigned long long r  = vr[k];   // packed vr pair (LDS.64, group-broadcast)
            unsigned long long ii = vi[k];   // packed vi pair
            FMA2(P, ka[k], r);
            FMA2(Q, kb[k], ii);
            FMA2(R, ka[k], ii);
            FMA2(S, kb[k], r);
        }
        float2 fP = up2(P), fQ = up2(Q), fR = up2(R), fS = up2(S);
        float ar = (fP.x + fP.y) + (fQ.x + fQ.y);
        float ai = (fR.x + fR.y) - (fS.x + fS.y);
        ar += __shfl_xor_sync(0xffffffffu, ar, 8);
        ai += __shfl_xor_sync(0xffffffffu, ai, 8);
        ar += __shfl_xor_sync(0xffffffffu, ar, 16);
        ai += __shfl_xor_sync(0xffffffffu, ai, 16);
        acc = fmaf(ar, ar, acc);
        acc = fmaf(ai, ai, acc);
    }

    if (lane < 8) atomicAdd(&out[b * NM + mi], acc * g_einv[b]);
}

// ---------------- entry point ----------------
extern "C" void kernel_launch(void* const* d_in, const int* in_sizes, int n_in,
                              void* d_out, int out_size) {
    const int*   x   = (const int*)  d_in[0];   // [B, L] int32
    const float* amp = (const float*)d_in[1];   // [VOCAB, D]
    const float* pha = (const float*)d_in[2];   // [VOCAB, D]
    const float* mix = (const float*)d_in[3];   // [VOCAB, 1]
    const float* kr  = (const float*)d_in[4];   // [M, D]
    const float* ki  = (const float*)d_in[5];   // [M, D]
    float* out = (float*)d_out;                 // [B, M]

    cudaMemsetAsync(out, 0, (size_t)NB * NM * sizeof(float));
    k_prep<<<NB + 1, NL>>>(x, mix, kr, ki);     // +1 block normalizes kernel rows
    k_gather<<<NB * NL / 8, 256>>>(x, amp, pha);
    k_main<<<NB * NCHUNK, 512>>>(out);
}